// round 5
// baseline (speedup 1.0000x reference)
#include <cuda_runtime.h>

#define NI      1022      // interior size (N-2)
#define NF      1024      // full size N
#define PITCH   1024      // padded row pitch (128B aligned)
#define BATCH   8
#define ROWS    8         // output rows per thread (single-step kernel)
#define TY      4         // thread rows per block (single-step kernel)

// fused kernel tile
#define FTX     64        // output tile width
#define FTY     32        // output tile height
#define FS      2         // halo for 2 fused steps
#define FW      (FTX + 2*FS)   // 68
#define FH      (FTY + 2*FS)   // 36
#define FTHREADS 256

__device__ float g_bufA[BATCH * NI * PITCH];
__device__ float g_bufB[BATCH * NI * PITCH];
__device__ float g_force[BATCH * NI * PITCH];
__device__ float g_coef[9];
__device__ float g_cf[1];

__constant__ float c_coef[9];

// --- fold mu/k1/k2/k3 into 10 scalars ---------------------------------------
__global__ void setup_coef_kernel(const float* __restrict__ mu,
                                  const float* __restrict__ k1,
                                  const float* __restrict__ k2,
                                  const float* __restrict__ k3) {
    float s3 = 0.0f;
    #pragma unroll
    for (int i = 0; i < 9; i++) s3 += k3[i];
    float inv = 1.0f / s3;
    #pragma unroll
    for (int i = 0; i < 9; i++) g_coef[i] = (k1[i] + k2[i]) * inv;
    const float Hval = 1.0f / (float)(NF - 1);
    g_cf[0] = Hval * Hval / (mu[0] * s3);
}

// --- force = f_interior * H^2/(mu*S3), pitch-1024, padding stays zero -------
__global__ void force_kernel(const float* __restrict__ f) {
    int x0 = (blockIdx.x * blockDim.x + threadIdx.x) * 4;
    int y  = blockIdx.y;
    int b  = blockIdx.z;
    if (x0 >= NI + 2) return;
    float cf = g_cf[0];
    const float* frow = f + ((size_t)b * NF + (y + 1)) * NF;
    float4 q0 = *(const float4*)(frow + x0);
    float v1 = q0.y, v2 = q0.z, v3 = q0.w;
    float v4 = (x0 + 4 < NF) ? frow[x0 + 4] : 0.0f;
    float* orow = g_force + ((size_t)b * NI + y) * PITCH;
    if (x0 + 3 < NI) {
        float4 o; o.x = v1 * cf; o.y = v2 * cf; o.z = v3 * cf; o.w = v4 * cf;
        *(float4*)(orow + x0) = o;
    } else {
        if (x0 + 0 < NI) orow[x0 + 0] = v1 * cf;
        if (x0 + 1 < NI) orow[x0 + 1] = v2 * cf;
        if (x0 + 2 < NI) orow[x0 + 2] = v3 * cf;
        if (x0 + 3 < NI) orow[x0 + 3] = v4 * cf;
    }
}

// --- fused horizontal conv helper (single-step kernel) -----------------------
__device__ __forceinline__ float4 hconv(float cA, float cB, float cC,
                                        float l, float4 v, float r) {
    float4 h;
    h.x = cA * l   + cB * v.x + cC * v.y;
    h.y = cA * v.x + cB * v.y + cC * v.z;
    h.z = cA * v.y + cB * v.z + cC * v.w;
    h.w = cA * v.z + cB * v.w + cC * r;
    return h;
}

// --- single Jacobi step (used for step 0: pre -> bufA) -----------------------
template<bool VEC_IN, bool VEC_OUT>
__global__ void __launch_bounds__(32 * TY)
step_kernel(const float* __restrict__ in, int in_pitch,
            float* __restrict__ out, int out_pitch) {
    const unsigned FULL = 0xffffffffu;
    int lane  = threadIdx.x;
    int x0    = (blockIdx.x * 32 + lane) * 4;
    int ybase = (blockIdx.y * TY + threadIdx.y) * ROWS;
    int b     = blockIdx.z;

    if (ybase >= NI) return;

    float c0 = c_coef[0], c1 = c_coef[1], c2 = c_coef[2];
    float c3 = c_coef[3], c4 = c_coef[4], c5 = c_coef[5];
    float c6 = c_coef[6], c7 = c_coef[7], c8 = c_coef[8];

    const float* src = in + (size_t)b * NI * in_pitch;

    float4 acc[ROWS];
    #pragma unroll
    for (int i = 0; i < ROWS; i++) {
        int row = ybase + i;
        if (row < NI) {
            acc[i] = *(const float4*)(g_force + ((size_t)b * NI + row) * PITCH + x0);
        } else {
            acc[i].x = acc[i].y = acc[i].z = acc[i].w = 0.0f;
        }
    }

    #pragma unroll
    for (int rj = 0; rj <= ROWS + 1; rj++) {
        int ri  = rj - 1;
        int row = ybase + ri;
        if (row < 0 || row >= NI) continue;

        const float* rp = src + (size_t)row * in_pitch;
        float4 v; float l, rr;
        if (VEC_IN) {
            v = *(const float4*)(rp + x0);
            l  = __shfl_up_sync(FULL, v.w, 1);
            if (lane == 0)  l  = (x0 > 0)      ? rp[x0 - 1] : 0.0f;
            rr = __shfl_down_sync(FULL, v.x, 1);
            if (lane == 31) rr = (x0 + 4 < NI) ? rp[x0 + 4] : 0.0f;
        } else {
            l   = (x0 - 1 >= 0 && x0 - 1 < NI) ? rp[x0 - 1] : 0.0f;
            v.x = (x0 + 0 < NI) ? rp[x0 + 0] : 0.0f;
            v.y = (x0 + 1 < NI) ? rp[x0 + 1] : 0.0f;
            v.z = (x0 + 2 < NI) ? rp[x0 + 2] : 0.0f;
            v.w = (x0 + 3 < NI) ? rp[x0 + 3] : 0.0f;
            rr  = (x0 + 4 < NI) ? rp[x0 + 4] : 0.0f;
        }

        if (ri + 1 >= 0 && ri + 1 < ROWS) {
            float4 h = hconv(c0, c1, c2, l, v, rr);
            acc[ri + 1].x += h.x; acc[ri + 1].y += h.y;
            acc[ri + 1].z += h.z; acc[ri + 1].w += h.w;
        }
        if (ri >= 0 && ri < ROWS) {
            float4 h = hconv(c3, c4, c5, l, v, rr);
            acc[ri].x += h.x; acc[ri].y += h.y;
            acc[ri].z += h.z; acc[ri].w += h.w;
        }
        if (ri - 1 >= 0 && ri - 1 < ROWS) {
            float4 h = hconv(c6, c7, c8, l, v, rr);
            acc[ri - 1].x += h.x; acc[ri - 1].y += h.y;
            acc[ri - 1].z += h.z; acc[ri - 1].w += h.w;
        }
    }

    #pragma unroll
    for (int i = 0; i < ROWS; i++) {
        int row = ybase + i;
        if (row >= NI) continue;
        float* orow = out + ((size_t)b * NI + row) * out_pitch;
        if (VEC_OUT) {
            if (x0 + 3 < NI) {
                *(float4*)(orow + x0) = acc[i];
            } else {
                if (x0 + 0 < NI) orow[x0 + 0] = acc[i].x;
                if (x0 + 1 < NI) orow[x0 + 1] = acc[i].y;
            }
        } else {
            if (x0 + 0 < NI) orow[x0 + 0] = acc[i].x;
            if (x0 + 1 < NI) orow[x0 + 1] = acc[i].y;
            if (x0 + 2 < NI) orow[x0 + 2] = acc[i].z;
            if (x0 + 3 < NI) orow[x0 + 3] = acc[i].w;
        }
    }
}

// --- fused 2-step Jacobi, simple & explicit ----------------------------------
// local (r,c) <-> global (ybase - FS + r, xbase - FS + c)
// stage 1: s_mid[r][c] = step(in) for r in [1,FH-1), c in [1,FW-1)
// stage 2: out(g)      = step(mid) for r in [2,FH-2), c in [2,FW-2)
template<bool COMPACT_OUT>
__global__ void __launch_bounds__(FTHREADS)
fused2_kernel(const float* __restrict__ in, int in_pitch,
              float* __restrict__ out, int out_pitch) {
    __shared__ float s_in [FH][FW];
    __shared__ float s_mid[FH][FW];

    int tid   = threadIdx.x;
    int xbase = blockIdx.x * FTX;
    int ybase = blockIdx.y * FTY;
    int b     = blockIdx.z;

    float c0 = c_coef[0], c1 = c_coef[1], c2 = c_coef[2];
    float c3 = c_coef[3], c4 = c_coef[4], c5 = c_coef[5];
    float c6 = c_coef[6], c7 = c_coef[7], c8 = c_coef[8];

    const float* src = in      + (size_t)b * NI * in_pitch;
    float*       dst = out     + (size_t)b * NI * out_pitch;   // FIX: batch offset
    const float* frc = g_force + (size_t)b * NI * PITCH;

    // ---- load input tile (zero outside domain = hard_encode pad) -----------
    for (int idx = tid; idx < FH * FW; idx += FTHREADS) {
        int r = idx / FW, c = idx % FW;
        int gy = ybase - FS + r, gx = xbase - FS + c;
        float v = 0.0f;
        if ((unsigned)gy < (unsigned)NI && (unsigned)gx < (unsigned)NI)
            v = src[(size_t)gy * in_pitch + gx];
        s_in[r][c] = v;
    }
    __syncthreads();

    // ---- stage 1: mid on rows 1..FH-2, cols 1..FW-2 (pairs of columns) -----
    {
        const int MH = FH - 2;          // 34 rows
        const int MG = (FW - 2) / 2;    // 33 column pairs (66 cols exactly)
        for (int idx = tid; idx < MH * MG; idx += FTHREADS) {
            int r = 1 + idx / MG;
            int c = 1 + 2 * (idx % MG);     // c, c+1
            float a0 = s_in[r-1][c-1], a1 = s_in[r-1][c], a2 = s_in[r-1][c+1], a3 = s_in[r-1][c+2];
            float b0 = s_in[r  ][c-1], b1 = s_in[r  ][c], b2 = s_in[r  ][c+1], b3 = s_in[r  ][c+2];
            float d0 = s_in[r+1][c-1], d1 = s_in[r+1][c], d2 = s_in[r+1][c+1], d3 = s_in[r+1][c+2];

            float convA = c0*a0 + c1*a1 + c2*a2
                        + c3*b0 + c4*b1 + c5*b2
                        + c6*d0 + c7*d1 + c8*d2;
            float convB = c0*a1 + c1*a2 + c2*a3
                        + c3*b1 + c4*b2 + c5*b3
                        + c6*d1 + c7*d2 + c8*d3;

            int gy  = ybase - FS + r;
            int gxA = xbase - FS + c;
            int gxB = gxA + 1;

            float vA = 0.0f, vB = 0.0f;
            if ((unsigned)gy < (unsigned)NI) {
                const float* fr = frc + (size_t)gy * PITCH;
                if ((unsigned)gxA < (unsigned)NI) vA = fr[gxA] + convA;
                if ((unsigned)gxB < (unsigned)NI) vB = fr[gxB] + convB;
            }
            s_mid[r][c]     = vA;
            s_mid[r][c + 1] = vB;
        }
    }
    __syncthreads();

    // ---- stage 2: out on rows 2..FH-3, cols 2..FW-3 (pairs of columns) -----
    {
        const int OG = FTX / 2;         // 32 column pairs
        for (int idx = tid; idx < FTY * OG; idx += FTHREADS) {
            int rr = idx / OG;              // 0..FTY-1
            int cc = 2 * (idx % OG);        // 0..FTX-2 step 2
            int r  = FS + rr;
            int c  = FS + cc;

            float a0 = s_mid[r-1][c-1], a1 = s_mid[r-1][c], a2 = s_mid[r-1][c+1], a3 = s_mid[r-1][c+2];
            float b0 = s_mid[r  ][c-1], b1 = s_mid[r  ][c], b2 = s_mid[r  ][c+1], b3 = s_mid[r  ][c+2];
            float d0 = s_mid[r+1][c-1], d1 = s_mid[r+1][c], d2 = s_mid[r+1][c+1], d3 = s_mid[r+1][c+2];

            float convA = c0*a0 + c1*a1 + c2*a2
                        + c3*b0 + c4*b1 + c5*b2
                        + c6*d0 + c7*d1 + c8*d2;
            float convB = c0*a1 + c1*a2 + c2*a3
                        + c3*b1 + c4*b2 + c5*b3
                        + c6*d1 + c7*d2 + c8*d3;

            int gy  = ybase + rr;
            int gxA = xbase + cc;
            int gxB = gxA + 1;
            if (gy >= NI) continue;

            const float* fr  = frc + (size_t)gy * PITCH;
            float* orow = dst + (size_t)gy * out_pitch;
            if (gxA < NI) orow[gxA] = fr[gxA] + convA;
            if (gxB < NI) orow[gxB] = fr[gxB] + convB;
        }
    }
}

extern "C" void kernel_launch(void* const* d_in, const int* in_sizes, int n_in,
                              void* d_out, int out_size) {
    // metadata order: x, pre, f, mu, k1, k2, k3  (x unused by the reference)
    const float* pre = (const float*)d_in[1];
    const float* f   = (const float*)d_in[2];
    const float* mu  = (const float*)d_in[3];
    const float* k1  = (const float*)d_in[4];
    const float* k2  = (const float*)d_in[5];
    const float* k3  = (const float*)d_in[6];
    float* out = (float*)d_out;

    void *pA = nullptr, *pB = nullptr, *pC = nullptr;
    cudaGetSymbolAddress(&pA, g_bufA);
    cudaGetSymbolAddress(&pB, g_bufB);
    cudaGetSymbolAddress(&pC, g_coef);

    setup_coef_kernel<<<1, 1>>>(mu, k1, k2, k3);
    cudaMemcpyToSymbolAsync(c_coef, pC, 9 * sizeof(float), 0,
                            cudaMemcpyDeviceToDevice);

    {   // force precompute
        dim3 blk(128, 1, 1);
        dim3 grd((NF / 4 + 127) / 128, NI, BATCH);
        force_kernel<<<grd, blk>>>(f);
    }

    // step 0 (single): pre (compact) -> bufA (pitch 1024)
    {
        dim3 blk(32, TY, 1);
        dim3 grd(NF / 128, (NI + TY * ROWS - 1) / (TY * ROWS), BATCH);
        step_kernel<false, true><<<grd, blk>>>(pre, NI, (float*)pA, PITCH);
    }

    // 5 fused double-steps: steps 1..10
    dim3 fblk(FTHREADS, 1, 1);
    dim3 fgrd((NI + FTX - 1) / FTX, (NI + FTY - 1) / FTY, BATCH);

    fused2_kernel<false><<<fgrd, fblk>>>((const float*)pA, PITCH, (float*)pB, PITCH);
    fused2_kernel<false><<<fgrd, fblk>>>((const float*)pB, PITCH, (float*)pA, PITCH);
    fused2_kernel<false><<<fgrd, fblk>>>((const float*)pA, PITCH, (float*)pB, PITCH);
    fused2_kernel<false><<<fgrd, fblk>>>((const float*)pB, PITCH, (float*)pA, PITCH);
    fused2_kernel<true ><<<fgrd, fblk>>>((const float*)pA, PITCH, out, NI);
}

// round 6
// speedup vs baseline: 1.4756x; 1.4756x over previous
#include <cuda_runtime.h>

#define NI      1022      // interior size (N-2)
#define NF      1024      // full size N
#define PITCH   1024      // padded row pitch (128B aligned)
#define BATCH   8
#define ROWS    8         // output rows per thread (single-step kernel)
#define TY      4         // thread rows per block (single-step kernel)
#define RROWS   16        // output rows per thread (fused rolling kernel)
#define FTY2    4         // thread.y per block (fused rolling kernel)

__device__ float g_bufA[BATCH * NI * PITCH];
__device__ float g_bufB[BATCH * NI * PITCH];
__device__ float g_force[BATCH * NI * PITCH];
__device__ float g_coef[9];
__device__ float g_cf[1];

__constant__ float c_coef[9];

// --- fold mu/k1/k2/k3 into 10 scalars ---------------------------------------
__global__ void setup_coef_kernel(const float* __restrict__ mu,
                                  const float* __restrict__ k1,
                                  const float* __restrict__ k2,
                                  const float* __restrict__ k3) {
    float s3 = 0.0f;
    #pragma unroll
    for (int i = 0; i < 9; i++) s3 += k3[i];
    float inv = 1.0f / s3;
    #pragma unroll
    for (int i = 0; i < 9; i++) g_coef[i] = (k1[i] + k2[i]) * inv;
    const float Hval = 1.0f / (float)(NF - 1);
    g_cf[0] = Hval * Hval / (mu[0] * s3);
}

// --- force = f_interior * H^2/(mu*S3), pitch-1024, padding stays zero -------
__global__ void force_kernel(const float* __restrict__ f) {
    int x0 = (blockIdx.x * blockDim.x + threadIdx.x) * 4;
    int y  = blockIdx.y;
    int b  = blockIdx.z;
    if (x0 >= NI + 2) return;
    float cf = g_cf[0];
    const float* frow = f + ((size_t)b * NF + (y + 1)) * NF;
    float4 q0 = *(const float4*)(frow + x0);
    float v1 = q0.y, v2 = q0.z, v3 = q0.w;
    float v4 = (x0 + 4 < NF) ? frow[x0 + 4] : 0.0f;
    float* orow = g_force + ((size_t)b * NI + y) * PITCH;
    if (x0 + 3 < NI) {
        float4 o; o.x = v1 * cf; o.y = v2 * cf; o.z = v3 * cf; o.w = v4 * cf;
        *(float4*)(orow + x0) = o;
    } else {
        if (x0 + 0 < NI) orow[x0 + 0] = v1 * cf;
        if (x0 + 1 < NI) orow[x0 + 1] = v2 * cf;
        if (x0 + 2 < NI) orow[x0 + 2] = v3 * cf;
        if (x0 + 3 < NI) orow[x0 + 3] = v4 * cf;
    }
}

// --- fused horizontal conv helper (single-step kernel) -----------------------
__device__ __forceinline__ float4 hconv(float cA, float cB, float cC,
                                        float l, float4 v, float r) {
    float4 h;
    h.x = cA * l   + cB * v.x + cC * v.y;
    h.y = cA * v.x + cB * v.y + cC * v.z;
    h.z = cA * v.y + cB * v.z + cC * v.w;
    h.w = cA * v.z + cB * v.w + cC * r;
    return h;
}

// --- single Jacobi step (used for step 0: pre -> bufA) -----------------------
template<bool VEC_IN, bool VEC_OUT>
__global__ void __launch_bounds__(32 * TY)
step_kernel(const float* __restrict__ in, int in_pitch,
            float* __restrict__ out, int out_pitch) {
    const unsigned FULL = 0xffffffffu;
    int lane  = threadIdx.x;
    int x0    = (blockIdx.x * 32 + lane) * 4;
    int ybase = (blockIdx.y * TY + threadIdx.y) * ROWS;
    int b     = blockIdx.z;

    if (ybase >= NI) return;

    float c0 = c_coef[0], c1 = c_coef[1], c2 = c_coef[2];
    float c3 = c_coef[3], c4 = c_coef[4], c5 = c_coef[5];
    float c6 = c_coef[6], c7 = c_coef[7], c8 = c_coef[8];

    const float* src = in + (size_t)b * NI * in_pitch;

    float4 acc[ROWS];
    #pragma unroll
    for (int i = 0; i < ROWS; i++) {
        int row = ybase + i;
        if (row < NI) {
            acc[i] = *(const float4*)(g_force + ((size_t)b * NI + row) * PITCH + x0);
        } else {
            acc[i].x = acc[i].y = acc[i].z = acc[i].w = 0.0f;
        }
    }

    #pragma unroll
    for (int rj = 0; rj <= ROWS + 1; rj++) {
        int ri  = rj - 1;
        int row = ybase + ri;
        if (row < 0 || row >= NI) continue;

        const float* rp = src + (size_t)row * in_pitch;
        float4 v; float l, rr;
        if (VEC_IN) {
            v = *(const float4*)(rp + x0);
            l  = __shfl_up_sync(FULL, v.w, 1);
            if (lane == 0)  l  = (x0 > 0)      ? rp[x0 - 1] : 0.0f;
            rr = __shfl_down_sync(FULL, v.x, 1);
            if (lane == 31) rr = (x0 + 4 < NI) ? rp[x0 + 4] : 0.0f;
        } else {
            l   = (x0 - 1 >= 0 && x0 - 1 < NI) ? rp[x0 - 1] : 0.0f;
            v.x = (x0 + 0 < NI) ? rp[x0 + 0] : 0.0f;
            v.y = (x0 + 1 < NI) ? rp[x0 + 1] : 0.0f;
            v.z = (x0 + 2 < NI) ? rp[x0 + 2] : 0.0f;
            v.w = (x0 + 3 < NI) ? rp[x0 + 3] : 0.0f;
            rr  = (x0 + 4 < NI) ? rp[x0 + 4] : 0.0f;
        }

        if (ri + 1 >= 0 && ri + 1 < ROWS) {
            float4 h = hconv(c0, c1, c2, l, v, rr);
            acc[ri + 1].x += h.x; acc[ri + 1].y += h.y;
            acc[ri + 1].z += h.z; acc[ri + 1].w += h.w;
        }
        if (ri >= 0 && ri < ROWS) {
            float4 h = hconv(c3, c4, c5, l, v, rr);
            acc[ri].x += h.x; acc[ri].y += h.y;
            acc[ri].z += h.z; acc[ri].w += h.w;
        }
        if (ri - 1 >= 0 && ri - 1 < ROWS) {
            float4 h = hconv(c6, c7, c8, l, v, rr);
            acc[ri - 1].x += h.x; acc[ri - 1].y += h.y;
            acc[ri - 1].z += h.z; acc[ri - 1].w += h.w;
        }
    }

    #pragma unroll
    for (int i = 0; i < ROWS; i++) {
        int row = ybase + i;
        if (row >= NI) continue;
        float* orow = out + ((size_t)b * NI + row) * out_pitch;
        if (VEC_OUT) {
            if (x0 + 3 < NI) {
                *(float4*)(orow + x0) = acc[i];
            } else {
                if (x0 + 0 < NI) orow[x0 + 0] = acc[i].x;
                if (x0 + 1 < NI) orow[x0 + 1] = acc[i].y;
            }
        } else {
            if (x0 + 0 < NI) orow[x0 + 0] = acc[i].x;
            if (x0 + 1 < NI) orow[x0 + 1] = acc[i].y;
            if (x0 + 2 < NI) orow[x0 + 2] = acc[i].z;
            if (x0 + 3 < NI) orow[x0 + 3] = acc[i].w;
        }
    }
}

// --- fused 2-step Jacobi, register-rolling, smem-free ------------------------
// Thread owns cols [x0, x0+4) and output rows [ybase, ybase+RROWS).
// Rolling over input rows r: mid row r-1 (6-wide, cols x0-1..x0+4) from input
// rows r-2..r (8-wide via shfl), output row r-2 (4-wide) from mid rows r-3..r-1.
// Input must be pitch-1024 with zero padding cols (g_bufA/g_bufB invariant).
template<bool COMPACT_OUT>
__global__ void __launch_bounds__(32 * FTY2)
fused2r_kernel(const float* __restrict__ in,
               float* __restrict__ out, int out_pitch) {
    const unsigned FULL = 0xffffffffu;
    const int lane  = threadIdx.x;
    const int x0    = (blockIdx.x * 32 + lane) * 4;
    const int ybase = (blockIdx.y * FTY2 + threadIdx.y) * RROWS;
    const int b     = blockIdx.z;

    const float c0 = c_coef[0], c1 = c_coef[1], c2 = c_coef[2];
    const float c3 = c_coef[3], c4 = c_coef[4], c5 = c_coef[5];
    const float c6 = c_coef[6], c7 = c_coef[7], c8 = c_coef[8];

    const float* src = in      + (size_t)b * NI * PITCH;
    const float* frc = g_force + (size_t)b * NI * PITCH;
    float*       dst = out     + (size_t)b * NI * out_pitch;

    const bool L0  = (lane == 0);
    const bool L31 = (lane == 31);

    float inA[8], inB[8], inC[8];   // input rows r-2, r-1, r (cols x0-2..x0+5)
    float mA[6],  mB[6],  mC[6];    // mid rows r-3, r-2, r-1 (cols x0-1..x0+4)
    float4 fA, fB;                  // force rows r-2, r-1

    #pragma unroll
    for (int i = 0; i < 8; i++) { inA[i] = 0.f; inB[i] = 0.f; inC[i] = 0.f; }
    #pragma unroll
    for (int i = 0; i < 6; i++) { mA[i] = 0.f; mB[i] = 0.f; mC[i] = 0.f; }
    fA.x = fA.y = fA.z = fA.w = 0.f;
    fB = fA;

    for (int it = 0; it < RROWS + 4; it++) {
        const int r = ybase - 2 + it;

        // ---- shift input window, load row r ----
        #pragma unroll
        for (int i = 0; i < 8; i++) { inA[i] = inB[i]; inB[i] = inC[i]; }
        {
            float4 v; v.x = v.y = v.z = v.w = 0.f;
            float l2 = 0.f, l1 = 0.f, r4 = 0.f, r5 = 0.f;
            if ((unsigned)r < (unsigned)NI) {
                const float* rp = src + (size_t)r * PITCH;
                v = *(const float4*)(rp + x0);
                if (L0) {
                    l2 = (x0 >= 2) ? rp[x0 - 2] : 0.f;
                    l1 = (x0 >= 1) ? rp[x0 - 1] : 0.f;
                }
                if (L31) {
                    r4 = (x0 + 4 < NI) ? rp[x0 + 4] : 0.f;
                    r5 = (x0 + 5 < NI) ? rp[x0 + 5] : 0.f;
                }
            }
            float sl2 = __shfl_up_sync(FULL, v.z, 1);
            float sl1 = __shfl_up_sync(FULL, v.w, 1);
            float sr4 = __shfl_down_sync(FULL, v.x, 1);
            float sr5 = __shfl_down_sync(FULL, v.y, 1);
            if (!L0)  { l2 = sl2; l1 = sl1; }
            if (!L31) { r4 = sr4; r5 = sr5; }
            inC[0] = l2;  inC[1] = l1;
            inC[2] = v.x; inC[3] = v.y; inC[4] = v.z; inC[5] = v.w;
            inC[6] = r4;  inC[7] = r5;
        }

        // ---- shift mid window + force, compute mid row rm = r-1 ----
        #pragma unroll
        for (int i = 0; i < 6; i++) { mA[i] = mB[i]; mB[i] = mC[i]; }
        fA = fB;

        const int rm = r - 1;
        {
            float4 f4; f4.x = f4.y = f4.z = f4.w = 0.f;
            float fl = 0.f, fr = 0.f;
            const bool rowok = ((unsigned)rm < (unsigned)NI);
            if (rowok) {
                const float* fp = frc + (size_t)rm * PITCH;
                f4 = *(const float4*)(fp + x0);
                if (L0)  fl = (x0 >= 1)     ? fp[x0 - 1] : 0.f;
                if (L31) fr = (x0 + 4 < NI) ? fp[x0 + 4] : 0.f;
            }
            float sfl = __shfl_up_sync(FULL, f4.w, 1);
            float sfr = __shfl_down_sync(FULL, f4.x, 1);
            if (!L0)  fl = sfl;
            if (!L31) fr = sfr;
            fB = f4;

            if (rowok) {
                float f6[6];
                f6[0] = fl;   f6[1] = f4.x; f6[2] = f4.y;
                f6[3] = f4.z; f6[4] = f4.w; f6[5] = fr;
                #pragma unroll
                for (int i = 0; i < 6; i++) {
                    int gc = x0 - 1 + i;
                    float vmid = f6[i]
                        + c0 * inA[i] + c1 * inA[i + 1] + c2 * inA[i + 2]
                        + c3 * inB[i] + c4 * inB[i + 1] + c5 * inB[i + 2]
                        + c6 * inC[i] + c7 * inC[i + 1] + c8 * inC[i + 2];
                    mC[i] = ((unsigned)gc < (unsigned)NI) ? vmid : 0.f;
                }
            } else {
                #pragma unroll
                for (int i = 0; i < 6; i++) mC[i] = 0.f;
            }
        }

        // ---- output row ro = r-2 ----
        const int ro = r - 2;
        if (ro >= ybase && ro < NI) {
            float o[4];
            #pragma unroll
            for (int j = 0; j < 4; j++) {
                o[j] = c0 * mA[j] + c1 * mA[j + 1] + c2 * mA[j + 2]
                     + c3 * mB[j] + c4 * mB[j + 1] + c5 * mB[j + 2]
                     + c6 * mC[j] + c7 * mC[j + 1] + c8 * mC[j + 2];
            }
            float* orow = dst + (size_t)ro * out_pitch;
            if (!COMPACT_OUT && x0 + 3 < NI) {
                float4 ov;
                ov.x = o[0] + fA.x; ov.y = o[1] + fA.y;
                ov.z = o[2] + fA.z; ov.w = o[3] + fA.w;
                *(float4*)(orow + x0) = ov;
            } else {
                if (x0 + 0 < NI) orow[x0 + 0] = o[0] + fA.x;
                if (x0 + 1 < NI) orow[x0 + 1] = o[1] + fA.y;
                if (x0 + 2 < NI) orow[x0 + 2] = o[2] + fA.z;
                if (x0 + 3 < NI) orow[x0 + 3] = o[3] + fA.w;
            }
        }
    }
}

extern "C" void kernel_launch(void* const* d_in, const int* in_sizes, int n_in,
                              void* d_out, int out_size) {
    // metadata order: x, pre, f, mu, k1, k2, k3  (x unused by the reference)
    const float* pre = (const float*)d_in[1];
    const float* f   = (const float*)d_in[2];
    const float* mu  = (const float*)d_in[3];
    const float* k1  = (const float*)d_in[4];
    const float* k2  = (const float*)d_in[5];
    const float* k3  = (const float*)d_in[6];
    float* out = (float*)d_out;

    void *pA = nullptr, *pB = nullptr, *pC = nullptr;
    cudaGetSymbolAddress(&pA, g_bufA);
    cudaGetSymbolAddress(&pB, g_bufB);
    cudaGetSymbolAddress(&pC, g_coef);

    setup_coef_kernel<<<1, 1>>>(mu, k1, k2, k3);
    cudaMemcpyToSymbolAsync(c_coef, pC, 9 * sizeof(float), 0,
                            cudaMemcpyDeviceToDevice);

    {   // force precompute
        dim3 blk(128, 1, 1);
        dim3 grd((NF / 4 + 127) / 128, NI, BATCH);
        force_kernel<<<grd, blk>>>(f);
    }

    // step 0 (single): pre (compact) -> bufA (pitch 1024)
    {
        dim3 blk(32, TY, 1);
        dim3 grd(NF / 128, (NI + TY * ROWS - 1) / (TY * ROWS), BATCH);
        step_kernel<false, true><<<grd, blk>>>(pre, NI, (float*)pA, PITCH);
    }

    // 5 fused double-steps: steps 1..10
    dim3 fblk(32, FTY2, 1);
    dim3 fgrd(NF / 128, (NI + FTY2 * RROWS - 1) / (FTY2 * RROWS), BATCH);

    fused2r_kernel<false><<<fgrd, fblk>>>((const float*)pA, (float*)pB, PITCH);
    fused2r_kernel<false><<<fgrd, fblk>>>((const float*)pB, (float*)pA, PITCH);
    fused2r_kernel<false><<<fgrd, fblk>>>((const float*)pA, (float*)pB, PITCH);
    fused2r_kernel<false><<<fgrd, fblk>>>((const float*)pB, (float*)pA, PITCH);
    fused2r_kernel<true ><<<fgrd, fblk>>>((const float*)pA, out, NI);
}